// round 11
// baseline (speedup 1.0000x reference)
#include <cuda_runtime.h>

#define NTH 256
#define BT  32
typedef unsigned long long ULL;

// Packed big weights: [m][k2(64)][jp(256)] float4 =
//   { W[2jp][2k2], W[2jp+1][2k2], W[2jp][2k2+1], W[2jp+1][2k2+1] }   (W row-major [512][128])
// m: 0 enc_Whh0, 1 enc_Wih1, 2 enc_Whh1, 3 dec_Whh0, 4 dec_Wih1, 5 dec_Whh1
__device__ float4 g_W2[6][64 * 256];
// Aux pairs (float2 units, 2560 total = 5120 floats):
//   IH block: floats [e*1536 + kin*512 + j]   = Wih0_e[j][kin]   (e in {0 enc,1 dec})
//   B  block: floats [3072 + e*1024 + l*512 + j] = b_e_l[j]
__device__ float2 g_AUX[2560];

__global__ void prep_w(const float* __restrict__ eWhh0, const float* __restrict__ eWih1,
                       const float* __restrict__ eWhh1, const float* __restrict__ dWhh0,
                       const float* __restrict__ dWih1, const float* __restrict__ dWhh1,
                       const float* __restrict__ eWih0, const float* __restrict__ dWih0,
                       const float* __restrict__ eb0,   const float* __restrict__ eb1,
                       const float* __restrict__ db0,   const float* __restrict__ db1)
{
    int idx = blockIdx.x * blockDim.x + threadIdx.x;
    if (idx < 6 * 65536) {
        int m = idx >> 16;
        int r = idx & 65535;
        int k2 = r >> 10;          // 0..63
        int rest = r & 1023;
        int jp = rest >> 2;        // 0..255
        int c = rest & 3;
        int j = jp * 2 + (c & 1);
        int k = k2 * 2 + (c >> 1);
        const float* src;
        switch (m) {
            case 0: src = eWhh0; break;
            case 1: src = eWih1; break;
            case 2: src = eWhh1; break;
            case 3: src = dWhh0; break;
            case 4: src = dWih1; break;
            default: src = dWhh1; break;
        }
        ((float*)g_W2)[idx] = src[j * 128 + k];
    } else if (idx < 6 * 65536 + 5120) {
        int i2 = idx - 6 * 65536;
        float v;
        if (i2 < 3072) {
            int e = i2 / 1536;
            int rem = i2 % 1536;
            int kin = rem / 512;
            int j = rem % 512;
            v = (e ? dWih0 : eWih0)[j * 3 + kin];
        } else {
            int i3 = i2 - 3072;
            int e = i3 / 1024;
            int rem = i3 % 1024;
            int layer = rem / 512;
            int j = rem % 512;
            const float* b = e ? (layer ? db1 : db0) : (layer ? eb1 : eb0);
            v = b[j];
        }
        ((float*)g_AUX)[i2] = v;
    }
}

struct SM {
    float2 h0d[128 * 34];   // [k][row] {h,h} duplicated; row stride 34 keeps 16B pairs aligned
    float2 h1d[128 * 34];
    float  c0[32 * 128];
    float  c1[32 * 128];
    float  xcur[32 * 4];
    float  fcWs[6 * 128];
    float  fcbs[8];
};

__device__ __forceinline__ float2 up2(ULL v) {
    float2 f;
    asm("mov.b64 {%0, %1}, %2;" : "=f"(f.x), "=f"(f.y) : "l"(v));
    return f;
}
__device__ __forceinline__ ULL pkdup(float v) {
    ULL r;
    asm("mov.b64 %0, {%1, %1};" : "=l"(r) : "f"(v));
    return r;
}
__device__ __forceinline__ float tfast(float x) {
    float y;
    asm("tanh.approx.f32 %0, %1;" : "=f"(y) : "f"(x));
    return y;
}
__device__ __forceinline__ float sigm(float x) {
    return fmaf(0.5f, tfast(0.5f * x), 0.5f);
}

// acc[g*8 + rr]: f32x2 lanes = gate outputs (j, j+1), j = g*128 + 2*jp0, row = r0+rr.
__device__ __forceinline__ void mv128(const float4* __restrict__ W2,
                                      const float2* __restrict__ Hd,
                                      int r0, int jp0, ULL* acc)
{
#pragma unroll 1
    for (int k2 = 0; k2 < 64; ++k2) {
        const float4* wp = W2 + k2 * 256 + jp0;
        ulonglong2 w0 = *(const ulonglong2*)(wp);
        ulonglong2 w1 = *(const ulonglong2*)(wp + 64);
        ulonglong2 w2 = *(const ulonglong2*)(wp + 128);
        ulonglong2 w3 = *(const ulonglong2*)(wp + 192);
        const float2* ha_base = Hd + (2 * k2) * 34 + r0;
#pragma unroll
        for (int p = 0; p < 4; ++p) {
            ulonglong2 ha = *(const ulonglong2*)(ha_base + 2 * p);        // k=2k2,   rows r0+2p, r0+2p+1
            ulonglong2 hb = *(const ulonglong2*)(ha_base + 34 + 2 * p);   // k=2k2+1
            asm("fma.rn.f32x2 %0, %1, %2, %0;" : "+l"(acc[0 * 8 + 2 * p    ]) : "l"(w0.x), "l"(ha.x));
            asm("fma.rn.f32x2 %0, %1, %2, %0;" : "+l"(acc[0 * 8 + 2 * p    ]) : "l"(w0.y), "l"(hb.x));
            asm("fma.rn.f32x2 %0, %1, %2, %0;" : "+l"(acc[0 * 8 + 2 * p + 1]) : "l"(w0.x), "l"(ha.y));
            asm("fma.rn.f32x2 %0, %1, %2, %0;" : "+l"(acc[0 * 8 + 2 * p + 1]) : "l"(w0.y), "l"(hb.y));
            asm("fma.rn.f32x2 %0, %1, %2, %0;" : "+l"(acc[1 * 8 + 2 * p    ]) : "l"(w1.x), "l"(ha.x));
            asm("fma.rn.f32x2 %0, %1, %2, %0;" : "+l"(acc[1 * 8 + 2 * p    ]) : "l"(w1.y), "l"(hb.x));
            asm("fma.rn.f32x2 %0, %1, %2, %0;" : "+l"(acc[1 * 8 + 2 * p + 1]) : "l"(w1.x), "l"(ha.y));
            asm("fma.rn.f32x2 %0, %1, %2, %0;" : "+l"(acc[1 * 8 + 2 * p + 1]) : "l"(w1.y), "l"(hb.y));
            asm("fma.rn.f32x2 %0, %1, %2, %0;" : "+l"(acc[2 * 8 + 2 * p    ]) : "l"(w2.x), "l"(ha.x));
            asm("fma.rn.f32x2 %0, %1, %2, %0;" : "+l"(acc[2 * 8 + 2 * p    ]) : "l"(w2.y), "l"(hb.x));
            asm("fma.rn.f32x2 %0, %1, %2, %0;" : "+l"(acc[2 * 8 + 2 * p + 1]) : "l"(w2.x), "l"(ha.y));
            asm("fma.rn.f32x2 %0, %1, %2, %0;" : "+l"(acc[2 * 8 + 2 * p + 1]) : "l"(w2.y), "l"(hb.y));
            asm("fma.rn.f32x2 %0, %1, %2, %0;" : "+l"(acc[3 * 8 + 2 * p    ]) : "l"(w3.x), "l"(ha.x));
            asm("fma.rn.f32x2 %0, %1, %2, %0;" : "+l"(acc[3 * 8 + 2 * p    ]) : "l"(w3.y), "l"(hb.x));
            asm("fma.rn.f32x2 %0, %1, %2, %0;" : "+l"(acc[3 * 8 + 2 * p + 1]) : "l"(w3.x), "l"(ha.y));
            asm("fma.rn.f32x2 %0, %1, %2, %0;" : "+l"(acc[3 * 8 + 2 * p + 1]) : "l"(w3.y), "l"(hb.y));
        }
    }
}

__device__ __forceinline__ void gate_update(const ULL* acc, float* __restrict__ cs,
                                            float2* __restrict__ Hd, int r0, int hh0)
{
#pragma unroll
    for (int r = 0; r < 8; ++r) {
        int row = r0 + r;
        float2 gi = up2(acc[0 * 8 + r]);
        float2 gf = up2(acc[1 * 8 + r]);
        float2 gg = up2(acc[2 * 8 + r]);
        float2 go = up2(acc[3 * 8 + r]);
        float2 c = *(float2*)&cs[row * 128 + hh0];
        float cx = sigm(gf.x) * c.x + sigm(gi.x) * tfast(gg.x);
        float cy = sigm(gf.y) * c.y + sigm(gi.y) * tfast(gg.y);
        float hx = sigm(go.x) * tfast(cx);
        float hy = sigm(go.y) * tfast(cy);
        *(float2*)&cs[row * 128 + hh0] = make_float2(cx, cy);
        Hd[hh0 * 34 + row] = make_float2(hx, hx);
        Hd[(hh0 + 1) * 34 + row] = make_float2(hy, hy);
    }
}

// One full 2-layer timestep for this CTA's 32 rows.
__device__ __forceinline__ void step(SM* sm,
                                     const float* __restrict__ xbase, int xstride, int xoff,
                                     const float2* __restrict__ ih0,
                                     const float2* __restrict__ b0,
                                     const float2* __restrict__ b1,
                                     const float4* __restrict__ W2hh0,
                                     const float4* __restrict__ W2ih1,
                                     const float4* __restrict__ W2hh1,
                                     int r0, int jp0, int hh0)
{
    ULL acc[32];

    // ---- layer 0 init: bias + Wih0 @ x (input dim 3) ----
    {
        ULL bb[4], ih[4][3];
#pragma unroll
        for (int g = 0; g < 4; ++g) {
            bb[g] = *(const ULL*)(b0 + g * 64 + jp0);
#pragma unroll
            for (int kin = 0; kin < 3; ++kin)
                ih[g][kin] = *(const ULL*)(ih0 + kin * 256 + g * 64 + jp0);
        }
#pragma unroll
        for (int r = 0; r < 8; ++r) {
            const float* xr = xbase + (size_t)(r0 + r) * xstride + xoff;
            ULL x0 = pkdup(xr[0]);
            ULL x1 = pkdup(xr[1]);
            ULL x2 = pkdup(xr[2]);
#pragma unroll
            for (int g = 0; g < 4; ++g) {
                ULL a = bb[g];
                asm("fma.rn.f32x2 %0, %1, %2, %0;" : "+l"(a) : "l"(ih[g][0]), "l"(x0));
                asm("fma.rn.f32x2 %0, %1, %2, %0;" : "+l"(a) : "l"(ih[g][1]), "l"(x1));
                asm("fma.rn.f32x2 %0, %1, %2, %0;" : "+l"(a) : "l"(ih[g][2]), "l"(x2));
                acc[g * 8 + r] = a;
            }
        }
    }
    mv128(W2hh0, sm->h0d, r0, jp0, acc);
    __syncthreads();                          // all reads of old h0 done
    gate_update(acc, sm->c0, sm->h0d, r0, hh0);
    __syncthreads();                          // new h0 visible

    // ---- layer 1: bias + Wih1 @ h0_new + Whh1 @ h1_old ----
#pragma unroll
    for (int g = 0; g < 4; ++g) {
        ULL bv = *(const ULL*)(b1 + g * 64 + jp0);
#pragma unroll
        for (int r = 0; r < 8; ++r) acc[g * 8 + r] = bv;
    }
    mv128(W2ih1, sm->h0d, r0, jp0, acc);
    mv128(W2hh1, sm->h1d, r0, jp0, acc);
    __syncthreads();                          // all reads of old h1 done
    gate_update(acc, sm->c1, sm->h1d, r0, hh0);
    __syncthreads();                          // new h1 visible
}

__global__ void __launch_bounds__(NTH, 2)
lstm_kernel(const float* __restrict__ x,
            const float* __restrict__ fcW, const float* __restrict__ fcb,
            float* __restrict__ out, int B)
{
    extern __shared__ char smraw[];
    SM* sm = (SM*)smraw;

    const int tid = threadIdx.x;
    const int r0 = (tid >> 6) * 8;     // 4 row groups of 8 rows
    const int hh0 = (tid & 63) * 2;    // 64 gate-pair groups
    const int jp0 = hh0 >> 1;
    const int bbase = blockIdx.x * BT;

    // zero duplicated-h and c state; stage fc weights
    for (int i = tid; i < 2 * 128 * 34; i += NTH) sm->h0d[i] = make_float2(0.f, 0.f);
    for (int i = tid; i < 2 * 32 * 128; i += NTH) sm->c0[i] = 0.f;
    for (int i = tid; i < 768; i += NTH) sm->fcWs[i] = fcW[i];
    if (tid < 6) sm->fcbs[tid] = fcb[tid];
    __syncthreads();

    const float2* AUX = g_AUX;

    // ---------------- encoder ----------------
    {
        const float2* ih0 = AUX;                  // e=0
        const float2* b0 = AUX + 1536;            // e=0, layer 0
        const float2* b1 = AUX + 1536 + 256;      // e=0, layer 1
        const float* xb = x + (size_t)bbase * 90;
        for (int t = 0; t < 30; ++t)
            step(sm, xb, 90, 3 * t, ih0, b0, b1,
                 (const float4*)g_W2[0], (const float4*)g_W2[1], (const float4*)g_W2[2],
                 r0, jp0, hh0);
    }

    // seed decoder input with x[:, -1, :]
    if (tid < 96) sm->xcur[(tid / 3) * 4 + (tid % 3)] =
        x[(size_t)(bbase + tid / 3) * 90 + 87 + (tid % 3)];
    __syncthreads();

    // ---------------- decoder ----------------
    const float2* ih0 = AUX + 768;                // e=1
    const float2* b0 = AUX + 1536 + 512;          // e=1, layer 0
    const float2* b1 = AUX + 1536 + 768;          // e=1, layer 1
    const size_t logvar_off = (size_t)B * 90;

    for (int t = 0; t < 30; ++t) {
        step(sm, sm->xcur, 4, 0, ih0, b0, b1,
             (const float4*)g_W2[3], (const float4*)g_W2[4], (const float4*)g_W2[5],
             r0, jp0, hh0);

        // fc: stats = h1 @ fc_W^T + fc_b  (6 outputs x 32 rows = 192 threads)
        if (tid < 192) {
            int row = tid & 31;
            int o = tid >> 5;       // 0..5
            const float* w = &sm->fcWs[o * 128];
            float s0 = 0.f, s1 = 0.f, s2 = 0.f, s3 = 0.f;
#pragma unroll 8
            for (int k = 0; k < 128; k += 4) {
                s0 += w[k]     * sm->h1d[(k)     * 34 + row].x;
                s1 += w[k + 1] * sm->h1d[(k + 1) * 34 + row].x;
                s2 += w[k + 2] * sm->h1d[(k + 2) * 34 + row].x;
                s3 += w[k + 3] * sm->h1d[(k + 3) * 34 + row].x;
            }
            float s = sm->fcbs[o] + (s0 + s1) + (s2 + s3);
            size_t base = ((size_t)(bbase + row) * 30 + t) * 3;
            if (o < 3) {
                out[base + o] = s;
                sm->xcur[row * 4 + o] = s;   // feedback for next step
            } else {
                out[logvar_off + base + (o - 3)] = s;
            }
        }
        __syncthreads();   // xcur visible for next timestep
    }
}

extern "C" void kernel_launch(void* const* d_in, const int* in_sizes, int n_in,
                              void* d_out, int out_size)
{
    const float* x     = (const float*)d_in[0];
    const float* eWih0 = (const float*)d_in[1];
    const float* eWhh0 = (const float*)d_in[2];
    const float* eb0   = (const float*)d_in[3];
    const float* eWih1 = (const float*)d_in[4];
    const float* eWhh1 = (const float*)d_in[5];
    const float* eb1   = (const float*)d_in[6];
    const float* dWih0 = (const float*)d_in[7];
    const float* dWhh0 = (const float*)d_in[8];
    const float* db0   = (const float*)d_in[9];
    const float* dWih1 = (const float*)d_in[10];
    const float* dWhh1 = (const float*)d_in[11];
    const float* db1   = (const float*)d_in[12];
    const float* fcW   = (const float*)d_in[13];
    const float* fcb   = (const float*)d_in[14];
    float* out = (float*)d_out;

    int B = in_sizes[0] / 90;   // T_IN * IN_DIM = 90

    cudaFuncSetAttribute(lstm_kernel, cudaFuncAttributeMaxDynamicSharedMemorySize,
                         (int)sizeof(SM));

    // Re-pack the six 512x128 matrices + small weights into interleaved layouts.
    int prep_n = 6 * 65536 + 5120;
    prep_w<<<(prep_n + 255) / 256, 256>>>(eWhh0, eWih1, eWhh1, dWhh0, dWih1, dWhh1,
                                          eWih0, dWih0, eb0, eb1, db0, db1);

    lstm_kernel<<<B / BT, NTH, sizeof(SM)>>>(x, fcW, fcb, out, B);
}

// round 12
// speedup vs baseline: 1.0087x; 1.0087x over previous
#include <cuda_runtime.h>

#define NTH 512
#define BT  32
typedef unsigned long long ULL;

// Pre-transposed big weights: [k (128)][j (512)], LDG.64 pair loads at (j, j+1).
// m: 0 enc_Whh0, 1 enc_Wih1, 2 enc_Whh1, 3 dec_Whh0, 4 dec_Wih1, 5 dec_Whh1
__device__ float g_WT[6][128 * 512];
// Aux floats (5120):
//   [e*1536 + kin*512 + j]          = Wih0_e[j][kin]      (e: 0 enc, 1 dec)
//   [3072 + e*1024 + l*512 + j]     = b_e_l[j]
__device__ float g_AUX[5120];

__global__ void prep_w(const float* __restrict__ eWhh0, const float* __restrict__ eWih1,
                       const float* __restrict__ eWhh1, const float* __restrict__ dWhh0,
                       const float* __restrict__ dWih1, const float* __restrict__ dWhh1,
                       const float* __restrict__ eWih0, const float* __restrict__ dWih0,
                       const float* __restrict__ eb0,   const float* __restrict__ eb1,
                       const float* __restrict__ db0,   const float* __restrict__ db1)
{
    int idx = blockIdx.x * blockDim.x + threadIdx.x;
    if (idx < 6 * 65536) {
        int m = idx >> 16;
        int r = idx & 65535;
        int j = r >> 7;       // 0..511
        int k = r & 127;      // 0..127
        const float* src;
        switch (m) {
            case 0: src = eWhh0; break;
            case 1: src = eWih1; break;
            case 2: src = eWhh1; break;
            case 3: src = dWhh0; break;
            case 4: src = dWih1; break;
            default: src = dWhh1; break;
        }
        g_WT[m][k * 512 + j] = src[j * 128 + k];
    } else if (idx < 6 * 65536 + 5120) {
        int i2 = idx - 6 * 65536;
        float v;
        if (i2 < 3072) {
            int e = i2 / 1536;
            int rem = i2 % 1536;
            int kin = rem / 512;
            int j = rem % 512;
            v = (e ? dWih0 : eWih0)[j * 3 + kin];
        } else {
            int i3 = i2 - 3072;
            int e = i3 / 1024;
            int rem = i3 % 1024;
            int layer = rem / 512;
            int j = rem % 512;
            const float* b = e ? (layer ? db1 : db0) : (layer ? eb1 : eb0);
            v = b[j];
        }
        g_AUX[i2] = v;
    }
}

struct SM {
    float2 h0d[128 * 33];   // [k][row] {h,h} duplicated; odd row-stride 33
    float2 h1d[128 * 33];
    float  c0[32 * 128];
    float  c1[32 * 128];
    float  xcur[32 * 4];
    float  fcWs[6 * 128];
    float  fcbs[8];
};

__device__ __forceinline__ float2 up2(ULL v) {
    float2 f;
    asm("mov.b64 {%0, %1}, %2;" : "=f"(f.x), "=f"(f.y) : "l"(v));
    return f;
}
__device__ __forceinline__ ULL pkdup(float v) {
    ULL r;
    asm("mov.b64 %0, {%1, %1};" : "=l"(r) : "f"(v));
    return r;
}
__device__ __forceinline__ float tfast(float x) {
    float y;
    asm("tanh.approx.f32 %0, %1;" : "=f"(y) : "f"(x));
    return y;
}
__device__ __forceinline__ float sigm(float x) {
    return fmaf(0.5f, tfast(0.5f * x), 0.5f);
}

// acc[g*4 + r]: f32x2 lanes = gate outputs (hh0, hh0+1), gate block g, row r0+r.
__device__ __forceinline__ void mv128(const float* __restrict__ WT,
                                      const float2* __restrict__ Hd,
                                      int r0, int hh0, ULL* acc)
{
    const float* wp = WT + hh0;
#pragma unroll 2
    for (int k = 0; k < 128; ++k) {
        const float* wk = wp + k * 512;
        ULL w0 = *(const ULL*)(wk);
        ULL w1 = *(const ULL*)(wk + 128);
        ULL w2 = *(const ULL*)(wk + 256);
        ULL w3 = *(const ULL*)(wk + 384);
        const float2* hb = Hd + k * 33 + r0;
        ULL h0 = *(const ULL*)(hb);
        ULL h1 = *(const ULL*)(hb + 1);
        ULL h2 = *(const ULL*)(hb + 2);
        ULL h3 = *(const ULL*)(hb + 3);
        asm("fma.rn.f32x2 %0, %1, %2, %0;" : "+l"(acc[0])  : "l"(w0), "l"(h0));
        asm("fma.rn.f32x2 %0, %1, %2, %0;" : "+l"(acc[1])  : "l"(w0), "l"(h1));
        asm("fma.rn.f32x2 %0, %1, %2, %0;" : "+l"(acc[2])  : "l"(w0), "l"(h2));
        asm("fma.rn.f32x2 %0, %1, %2, %0;" : "+l"(acc[3])  : "l"(w0), "l"(h3));
        asm("fma.rn.f32x2 %0, %1, %2, %0;" : "+l"(acc[4])  : "l"(w1), "l"(h0));
        asm("fma.rn.f32x2 %0, %1, %2, %0;" : "+l"(acc[5])  : "l"(w1), "l"(h1));
        asm("fma.rn.f32x2 %0, %1, %2, %0;" : "+l"(acc[6])  : "l"(w1), "l"(h2));
        asm("fma.rn.f32x2 %0, %1, %2, %0;" : "+l"(acc[7])  : "l"(w1), "l"(h3));
        asm("fma.rn.f32x2 %0, %1, %2, %0;" : "+l"(acc[8])  : "l"(w2), "l"(h0));
        asm("fma.rn.f32x2 %0, %1, %2, %0;" : "+l"(acc[9])  : "l"(w2), "l"(h1));
        asm("fma.rn.f32x2 %0, %1, %2, %0;" : "+l"(acc[10]) : "l"(w2), "l"(h2));
        asm("fma.rn.f32x2 %0, %1, %2, %0;" : "+l"(acc[11]) : "l"(w2), "l"(h3));
        asm("fma.rn.f32x2 %0, %1, %2, %0;" : "+l"(acc[12]) : "l"(w3), "l"(h0));
        asm("fma.rn.f32x2 %0, %1, %2, %0;" : "+l"(acc[13]) : "l"(w3), "l"(h1));
        asm("fma.rn.f32x2 %0, %1, %2, %0;" : "+l"(acc[14]) : "l"(w3), "l"(h2));
        asm("fma.rn.f32x2 %0, %1, %2, %0;" : "+l"(acc[15]) : "l"(w3), "l"(h3));
    }
}

__device__ __forceinline__ void gate_update(const ULL* acc, float* __restrict__ cs,
                                            float2* __restrict__ Hd, int r0, int hh0)
{
#pragma unroll
    for (int r = 0; r < 4; ++r) {
        int row = r0 + r;
        float2 gi = up2(acc[0 * 4 + r]);
        float2 gf = up2(acc[1 * 4 + r]);
        float2 gg = up2(acc[2 * 4 + r]);
        float2 go = up2(acc[3 * 4 + r]);
        float2 c = *(float2*)&cs[row * 128 + hh0];
        float cx = sigm(gf.x) * c.x + sigm(gi.x) * tfast(gg.x);
        float cy = sigm(gf.y) * c.y + sigm(gi.y) * tfast(gg.y);
        float hx = sigm(go.x) * tfast(cx);
        float hy = sigm(go.y) * tfast(cy);
        *(float2*)&cs[row * 128 + hh0] = make_float2(cx, cy);
        Hd[hh0 * 33 + row] = make_float2(hx, hx);
        Hd[(hh0 + 1) * 33 + row] = make_float2(hy, hy);
    }
}

// One full 2-layer timestep for this CTA's 32 rows (thread: 4 rows x gate-pair).
__device__ __forceinline__ void step(SM* sm, const float xv[4][3],
                                     const float* __restrict__ ih0,
                                     const float* __restrict__ b0,
                                     const float* __restrict__ b1,
                                     const float* __restrict__ WThh0,
                                     const float* __restrict__ WTih1,
                                     const float* __restrict__ WThh1,
                                     int r0, int hh0)
{
    ULL acc[16];

    // ---- layer 0 init: bias + Wih0 @ x (input dim 3) ----
#pragma unroll
    for (int g = 0; g < 4; ++g) {
        const int j = g * 128 + hh0;
        ULL bb = *(const ULL*)(b0 + j);
        ULL w0 = *(const ULL*)(ih0 + j);
        ULL w1 = *(const ULL*)(ih0 + 512 + j);
        ULL w2 = *(const ULL*)(ih0 + 1024 + j);
#pragma unroll
        for (int r = 0; r < 4; ++r) {
            ULL a = bb;
            asm("fma.rn.f32x2 %0, %1, %2, %0;" : "+l"(a) : "l"(w0), "l"(pkdup(xv[r][0])));
            asm("fma.rn.f32x2 %0, %1, %2, %0;" : "+l"(a) : "l"(w1), "l"(pkdup(xv[r][1])));
            asm("fma.rn.f32x2 %0, %1, %2, %0;" : "+l"(a) : "l"(w2), "l"(pkdup(xv[r][2])));
            acc[g * 4 + r] = a;
        }
    }
    mv128(WThh0, sm->h0d, r0, hh0, acc);
    __syncthreads();                          // all reads of old h0 done
    gate_update(acc, sm->c0, sm->h0d, r0, hh0);
    __syncthreads();                          // new h0 visible

    // ---- layer 1: bias + Wih1 @ h0_new + Whh1 @ h1_old ----
#pragma unroll
    for (int g = 0; g < 4; ++g) {
        ULL bv = *(const ULL*)(b1 + g * 128 + hh0);
#pragma unroll
        for (int r = 0; r < 4; ++r) acc[g * 4 + r] = bv;
    }
    mv128(WTih1, sm->h0d, r0, hh0, acc);
    mv128(WThh1, sm->h1d, r0, hh0, acc);
    __syncthreads();                          // all reads of old h1 done
    gate_update(acc, sm->c1, sm->h1d, r0, hh0);
    __syncthreads();                          // new h1 visible
}

__global__ void __launch_bounds__(NTH, 2)
lstm_kernel(const float* __restrict__ x,
            const float* __restrict__ fcW, const float* __restrict__ fcb,
            float* __restrict__ out, int B)
{
    extern __shared__ char smraw[];
    SM* sm = (SM*)smraw;

    const int tid = threadIdx.x;
    const int r0 = (tid >> 6) * 4;     // 8 row groups of 4 rows
    const int hh0 = (tid & 63) * 2;    // 64 gate-pair groups
    const int bbase = blockIdx.x * BT;

    // zero duplicated-h and c state; stage fc weights
    for (int i = tid; i < 2 * 128 * 33; i += NTH) sm->h0d[i] = make_float2(0.f, 0.f);
    for (int i = tid; i < 2 * 32 * 128; i += NTH) sm->c0[i] = 0.f;
    for (int i = tid; i < 768; i += NTH) sm->fcWs[i] = fcW[i];
    if (tid < 6) sm->fcbs[tid] = fcb[tid];
    __syncthreads();

    // ---------------- encoder ----------------
    {
        const float* ih0 = g_AUX;                 // e=0
        const float* b0 = g_AUX + 3072;           // e=0, layer 0
        const float* b1 = g_AUX + 3584;           // e=0, layer 1
        for (int t = 0; t < 30; ++t) {
            float xv[4][3];
#pragma unroll
            for (int r = 0; r < 4; ++r) {
                const float* xr = x + (size_t)(bbase + r0 + r) * 90 + 3 * t;
                xv[r][0] = xr[0];
                xv[r][1] = xr[1];
                xv[r][2] = xr[2];
            }
            step(sm, xv, ih0, b0, b1, g_WT[0], g_WT[1], g_WT[2], r0, hh0);
        }
    }

    // seed decoder input with x[:, -1, :]
    if (tid < 96) sm->xcur[(tid / 3) * 4 + (tid % 3)] =
        x[(size_t)(bbase + tid / 3) * 90 + 87 + (tid % 3)];
    __syncthreads();

    // ---------------- decoder ----------------
    const float* ih0 = g_AUX + 1536;              // e=1
    const float* b0 = g_AUX + 4096;               // e=1, layer 0
    const float* b1 = g_AUX + 4608;               // e=1, layer 1
    const size_t logvar_off = (size_t)B * 90;

    for (int t = 0; t < 30; ++t) {
        float xv[4][3];
#pragma unroll
        for (int r = 0; r < 4; ++r) {
            xv[r][0] = sm->xcur[(r0 + r) * 4 + 0];
            xv[r][1] = sm->xcur[(r0 + r) * 4 + 1];
            xv[r][2] = sm->xcur[(r0 + r) * 4 + 2];
        }
        step(sm, xv, ih0, b0, b1, g_WT[3], g_WT[4], g_WT[5], r0, hh0);

        // fc: stats = h1 @ fc_W^T + fc_b  (6 outputs x 32 rows = 192 threads)
        if (tid < 192) {
            int row = tid & 31;
            int o = tid >> 5;       // 0..5
            const float* w = &sm->fcWs[o * 128];
            float s0 = 0.f, s1 = 0.f, s2 = 0.f, s3 = 0.f;
#pragma unroll 8
            for (int k = 0; k < 128; k += 4) {
                s0 += w[k]     * sm->h1d[(k)     * 33 + row].x;
                s1 += w[k + 1] * sm->h1d[(k + 1) * 33 + row].x;
                s2 += w[k + 2] * sm->h1d[(k + 2) * 33 + row].x;
                s3 += w[k + 3] * sm->h1d[(k + 3) * 33 + row].x;
            }
            float s = sm->fcbs[o] + (s0 + s1) + (s2 + s3);
            size_t base = ((size_t)(bbase + row) * 30 + t) * 3;
            if (o < 3) {
                out[base + o] = s;
                sm->xcur[row * 4 + o] = s;   // feedback for next step
            } else {
                out[logvar_off + base + (o - 3)] = s;
            }
        }
        __syncthreads();   // xcur visible for next timestep
    }
}

extern "C" void kernel_launch(void* const* d_in, const int* in_sizes, int n_in,
                              void* d_out, int out_size)
{
    const float* x     = (const float*)d_in[0];
    const float* eWih0 = (const float*)d_in[1];
    const float* eWhh0 = (const float*)d_in[2];
    const float* eb0   = (const float*)d_in[3];
    const float* eWih1 = (const float*)d_in[4];
    const float* eWhh1 = (const float*)d_in[5];
    const float* eb1   = (const float*)d_in[6];
    const float* dWih0 = (const float*)d_in[7];
    const float* dWhh0 = (const float*)d_in[8];
    const float* db0   = (const float*)d_in[9];
    const float* dWih1 = (const float*)d_in[10];
    const float* dWhh1 = (const float*)d_in[11];
    const float* db1   = (const float*)d_in[12];
    const float* fcW   = (const float*)d_in[13];
    const float* fcb   = (const float*)d_in[14];
    float* out = (float*)d_out;

    int B = in_sizes[0] / 90;   // T_IN * IN_DIM = 90

    cudaFuncSetAttribute(lstm_kernel, cudaFuncAttributeMaxDynamicSharedMemorySize,
                         (int)sizeof(SM));

    int prep_n = 6 * 65536 + 5120;
    prep_w<<<(prep_n + 255) / 256, 256>>>(eWhh0, eWih1, eWhh1, dWhh0, dWih1, dWhh1,
                                          eWih0, dWih0, eb0, eb1, db0, db1);

    lstm_kernel<<<B / BT, NTH, sizeof(SM)>>>(x, fcW, fcb, out, B);
}